// round 9
// baseline (speedup 1.0000x reference)
#include <cuda_runtime.h>
#include <cuda_bf16.h>
#include <cstdint>

// ---------------------------------------------------------------------------
// total = -(1/L) * sum_i dot(q_hat_i, q_real_i)
//       + sum_{i,j} max(0, <pred_i, gt_j> - <pred_i, gt_i> + 1)
// L=8192, B=4096, D=1024.
// R9: CTA tile 256x128 (512 thr, 16 warps 4x4, warp tile 64x32 kept) ->
// 8 warps/SMSP at 2 CTAs/SM with the good MMA:LDSM ratio. 2-stage pipeline,
// single sync per chunk. finalize fused into the GEMM last CTA (ticket +
// spin on local_done). local_kernel overlapped on a side stream.
// ---------------------------------------------------------------------------

#define L_DIM 8192
#define B_DIM 4096
#define D_DIM 1024

struct Accum {
    double glob;
    double local;
    unsigned int gticket;
    unsigned int lticket;
    unsigned int local_done;
};
__device__ Accum g_acc;
__device__ float g_pos[B_DIM];
// FP8 operand buffers (4 MB each), stored as uint32 (4 e4m3 per word)
__device__ uint32_t g_predq[(size_t)B_DIM * D_DIM / 4];
__device__ uint32_t g_gtq[(size_t)B_DIM * D_DIM / 4];

#define GRID_X 32          // N tiles (128 each)
#define GRID_Y 16          // M tiles (256 each)
#define NUM_GEMM_CTAS (GRID_X * GRID_Y)
#define NUM_LOCAL_CTAS 1024

// ---------------------------------------------------------------------------
__device__ __forceinline__ uint32_t smem_u32(const void* p) {
    uint32_t a;
    asm("{ .reg .u64 t; cvta.to.shared.u64 t, %1; cvt.u32.u64 %0, t; }"
        : "=r"(a) : "l"(p));
    return a;
}

__device__ __forceinline__ void cp_async16(uint32_t smem, const void* gmem) {
    asm volatile("cp.async.cg.shared.global [%0], [%1], 16;"
                 :: "r"(smem), "l"(gmem) : "memory");
}
#define CP_COMMIT() asm volatile("cp.async.commit_group;" ::: "memory")
#define CP_WAIT1()  asm volatile("cp.async.wait_group 1;" ::: "memory")

#define LDSM_X4(r0, r1, r2, r3, addr) \
    asm volatile("ldmatrix.sync.aligned.m8n8.x4.shared.b16 {%0,%1,%2,%3}, [%4];" \
                 : "=r"(r0), "=r"(r1), "=r"(r2), "=r"(r3) : "r"(addr))

// FP8 e4m3 MMA, k32, fp32 accumulation.
__device__ __forceinline__ void mma16832(float* c, const uint32_t* a,
                                         uint32_t b0, uint32_t b1) {
    asm volatile(
        "mma.sync.aligned.m16n8k32.row.col.f32.e4m3.e4m3.f32 "
        "{%0,%1,%2,%3}, {%4,%5,%6,%7}, {%8,%9}, {%0,%1,%2,%3};"
        : "+f"(c[0]), "+f"(c[1]), "+f"(c[2]), "+f"(c[3])
        : "r"(a[0]), "r"(a[1]), "r"(a[2]), "r"(a[3]), "r"(b0), "r"(b1));
}

__device__ __forceinline__ uint32_t pack_e4m3x4(float4 v) {
    uint16_t lo, hi;
    asm("cvt.rn.satfinite.e4m3x2.f32 %0, %1, %2;" : "=h"(lo) : "f"(v.y), "f"(v.x));
    asm("cvt.rn.satfinite.e4m3x2.f32 %0, %1, %2;" : "=h"(hi) : "f"(v.w), "f"(v.z));
    return (uint32_t)lo | ((uint32_t)hi << 16);
}

// ---------------------------------------------------------------------------
// Kernel 1: fp32 -> e4m3 for pred/gt + pos[i] = dot(pred_i, gt_i) (exact fp32)
// ---------------------------------------------------------------------------
__global__ void prep_kernel(const float* __restrict__ pred,
                            const float* __restrict__ gt) {
    const int r = blockIdx.x;
    const int t = threadIdx.x;
    const float4 pv = ((const float4*)(pred + (size_t)r * D_DIM))[t];
    const float4 gv = ((const float4*)(gt + (size_t)r * D_DIM))[t];

    float acc = pv.x * gv.x + pv.y * gv.y + pv.z * gv.z + pv.w * gv.w;

    g_predq[(size_t)r * (D_DIM / 4) + t] = pack_e4m3x4(pv);
    g_gtq[(size_t)r * (D_DIM / 4) + t] = pack_e4m3x4(gv);

    #pragma unroll
    for (int o = 16; o > 0; o >>= 1)
        acc += __shfl_xor_sync(0xFFFFFFFFu, acc, o);
    __shared__ float ws[8];
    if ((t & 31) == 0) ws[t >> 5] = acc;
    __syncthreads();
    if (t == 0) {
        float s = 0.f;
        #pragma unroll
        for (int w = 0; w < 8; w++) s += ws[w];
        g_pos[r] = s;
    }
}

// ---------------------------------------------------------------------------
// Kernel 2: local loss partial (side stream; overlaps prep + GEMM).
// Last block sets local_done (release) for the GEMM's fused finalize.
// ---------------------------------------------------------------------------
__global__ void local_kernel(const float* __restrict__ a,
                             const float* __restrict__ b) {
    const size_t n4 = (size_t)L_DIM * D_DIM / 4;
    float acc = 0.f;
    for (size_t i = (size_t)blockIdx.x * blockDim.x + threadIdx.x; i < n4;
         i += (size_t)gridDim.x * blockDim.x) {
        float4 av = ((const float4*)a)[i];
        float4 bv = ((const float4*)b)[i];
        acc += av.x * bv.x + av.y * bv.y + av.z * bv.z + av.w * bv.w;
    }
    #pragma unroll
    for (int o = 16; o > 0; o >>= 1)
        acc += __shfl_xor_sync(0xFFFFFFFFu, acc, o);
    __shared__ float ws[8];
    const int t = threadIdx.x;
    if ((t & 31) == 0) ws[t >> 5] = acc;
    __syncthreads();
    if (t == 0) {
        float s = 0.f;
        #pragma unroll
        for (int w = 0; w < 8; w++) s += ws[w];
        atomicAdd(&g_acc.local, (double)s);
        __threadfence();
        unsigned int tk = atomicAdd(&g_acc.lticket, 1u);
        if (tk == NUM_LOCAL_CTAS - 1) {
            __threadfence();
            atomicExch(&g_acc.local_done, 1u);
        }
    }
}

// ---------------------------------------------------------------------------
// Kernel 3: FP8 GEMM 256x128 tile + fused hinge + fused finalize.
// grid = (32, 16), 512 threads (16 warps: 4(m) x 4(n), warp tile 64x32).
// BK = 128 fp8 -> stage = A 32 KB + B 16 KB = 48 KB, 2 stages (96 KB),
// 2 CTAs/SM = 8 warps/SMSP. Single __syncthreads per K-chunk.
// ---------------------------------------------------------------------------
static constexpr int STAGE_BYTES = 49152;           // 32K A + 16K B
static constexpr int GEMM_SMEM_DYN = 2 * STAGE_BYTES;  // 96 KB

__global__ void __launch_bounds__(512, 2) gemm_hinge_kernel(float* out) {
    extern __shared__ char smem_raw[];
    const uint32_t sb = smem_u32(smem_raw);
    const int tid = threadIdx.x;
    const int wid = tid >> 5;
    const int lane = tid & 31;
    const int warp_m = wid >> 2;   // 0..3 (64 rows each)
    const int warp_n = wid & 3;    // 0..3 (32 cols each)

    const uint8_t* __restrict__ Ab =
        (const uint8_t*)g_predq + (size_t)blockIdx.y * 256 * D_DIM;
    const uint8_t* __restrict__ Bb =
        (const uint8_t*)g_gtq + (size_t)blockIdx.x * 128 * D_DIM;

    // Precomputed LDSM base offsets: addr = stage_base + (base ^ (chunk<<4))
    uint32_t a_base[4], b_base[2];
    #pragma unroll
    for (int mt = 0; mt < 4; mt++) {
        const int row = warp_m * 64 + mt * 16 + (lane & 15);
        a_base[mt] = row * 128 + (((lane >> 4) ^ (row & 7)) << 4);
    }
    #pragma unroll
    for (int nt = 0; nt < 2; nt++) {
        const int row = warp_n * 32 + nt * 16 + (lane & 15);
        b_base[nt] = row * 128 + (((lane >> 4) ^ (row & 7)) << 4);
    }

    float acc[4][4][4];
    #pragma unroll
    for (int i = 0; i < 4; i++)
        #pragma unroll
        for (int j = 0; j < 4; j++)
            #pragma unroll
            for (int e = 0; e < 4; e++) acc[i][j][e] = 0.f;

    // Load one K-chunk: A 256 rows x 128 B, B 128 rows x 128 B, into stage st.
    auto load_stage = [&](int kc, int st) {
        const uint32_t baseA = sb + st * STAGE_BYTES;
        const uint32_t baseB = baseA + 32768;
        #pragma unroll
        for (int i = 0; i < 4; i++) {          // A: 2048 16B vectors
            const int idx = tid + i * 512;     // 0..2047
            const int row = idx >> 3;          // 0..255
            const int c = idx & 7;
            const uint32_t soff = row * 128 + ((c ^ (row & 7)) << 4);
            cp_async16(baseA + soff, Ab + (size_t)row * D_DIM + kc * 128 + c * 16);
        }
        #pragma unroll
        for (int i = 0; i < 2; i++) {          // B: 1024 16B vectors
            const int idx = tid + i * 512;     // 0..1023
            const int row = idx >> 3;          // 0..127
            const int c = idx & 7;
            const uint32_t soff = row * 128 + ((c ^ (row & 7)) << 4);
            cp_async16(baseB + soff, Bb + (size_t)row * D_DIM + kc * 128 + c * 16);
        }
    };

    load_stage(0, 0); CP_COMMIT();

    #pragma unroll 1
    for (int kc = 0; kc < 8; ++kc) {
        // Barrier first: ensures every warp finished compute(kc-1), so the
        // buffer (kc+1)&1 (== (kc-1)&1) is safe to overwrite.
        __syncthreads();
        if (kc + 1 < 8) load_stage(kc + 1, (kc + 1) & 1);
        CP_COMMIT();         // uniform group count even when empty
        CP_WAIT1();          // all-but-one outstanding -> group kc complete

        const uint32_t baseA = sb + (kc & 1) * STAGE_BYTES;
        const uint32_t baseB = baseA + 32768;

        #pragma unroll
        for (int ks = 0; ks < 4; ks++) {   // four k32 steps per 128-B chunk
            const uint32_t cx = (uint32_t)(ks * 2) << 4;
            uint32_t a[4][4], b[2][4];
            #pragma unroll
            for (int nt = 0; nt < 2; nt++)
                LDSM_X4(b[nt][0], b[nt][1], b[nt][2], b[nt][3],
                        baseB + (b_base[nt] ^ cx));
            #pragma unroll
            for (int mt = 0; mt < 4; mt++)
                LDSM_X4(a[mt][0], a[mt][1], a[mt][2], a[mt][3],
                        baseA + (a_base[mt] ^ cx));
            #pragma unroll
            for (int mt = 0; mt < 4; mt++)
                #pragma unroll
                for (int nt = 0; nt < 4; nt++)
                    mma16832(acc[mt][nt], a[mt],
                             b[nt >> 1][nt & 1], b[nt >> 1][(nt & 1) + 2]);
        }
    }

    // ---- fused hinge epilogue ----
    float partial = 0.f;
    #pragma unroll
    for (int mt = 0; mt < 4; mt++) {
        const int r0 = blockIdx.y * 256 + warp_m * 64 + mt * 16 + (lane >> 2);
        const float p0 = __ldg(&g_pos[r0]) - 1.0f;   // v - pos + 1 = v - (pos-1)
        const float p1 = __ldg(&g_pos[r0 + 8]) - 1.0f;
        #pragma unroll
        for (int nt = 0; nt < 4; nt++) {
            partial += fmaxf(acc[mt][nt][0] - p0, 0.f);
            partial += fmaxf(acc[mt][nt][1] - p0, 0.f);
            partial += fmaxf(acc[mt][nt][2] - p1, 0.f);
            partial += fmaxf(acc[mt][nt][3] - p1, 0.f);
        }
    }

    #pragma unroll
    for (int o = 16; o > 0; o >>= 1)
        partial += __shfl_xor_sync(0xFFFFFFFFu, partial, o);
    __shared__ float warpsum[16];
    if (lane == 0) warpsum[wid] = partial;
    __syncthreads();
    if (tid == 0) {
        float s = 0.f;
        #pragma unroll
        for (int w = 0; w < 16; w++) s += warpsum[w];
        atomicAdd(&g_acc.glob, (double)s);
        __threadfence();
        unsigned int tk = atomicAdd(&g_acc.gticket, 1u);
        if (tk == NUM_GEMM_CTAS - 1) {
            // Fused finalize: wait for local_kernel completion (side stream;
            // submitted before this kernel, independent of it — no deadlock).
            while (atomicAdd(&g_acc.local_done, 0u) == 0u) {}
            __threadfence();
            const double gv = *((volatile double*)&g_acc.glob);
            const double lv = *((volatile double*)&g_acc.local);
            out[0] = (float)(gv - lv / (double)L_DIM);
        }
    }
}

// ---------------------------------------------------------------------------
extern "C" void kernel_launch(void* const* d_in, const int* in_sizes, int n_in,
                              void* d_out, int out_size) {
    const float* q_hat  = (const float*)d_in[0];
    const float* q_real = (const float*)d_in[1];
    const float* gt     = (const float*)d_in[2];
    const float* pred   = (const float*)d_in[3];

    (void)in_sizes; (void)n_in; (void)out_size;

    // One-time setup on the first (non-captured) correctness call.
    static cudaStream_t s_side = nullptr;
    static cudaEvent_t ev_fork = nullptr, ev_join = nullptr;
    static void* accum_ptr = nullptr;
    if (!accum_ptr) {
        cudaFuncSetAttribute(gemm_hinge_kernel,
                             cudaFuncAttributeMaxDynamicSharedMemorySize,
                             GEMM_SMEM_DYN);
        cudaStreamCreateWithFlags(&s_side, cudaStreamNonBlocking);
        cudaEventCreateWithFlags(&ev_fork, cudaEventDisableTiming);
        cudaEventCreateWithFlags(&ev_join, cudaEventDisableTiming);
        cudaGetSymbolAddress(&accum_ptr, g_acc);
    }

    // Main stream: memset -> prep -> gemm(+finalize)
    // Side stream: local_kernel (independent; overlaps prep + gemm)
    cudaMemsetAsync(accum_ptr, 0, sizeof(Accum), 0);
    cudaEventRecord(ev_fork, 0);
    cudaStreamWaitEvent(s_side, ev_fork, 0);

    prep_kernel<<<B_DIM, 256>>>(pred, gt);
    local_kernel<<<NUM_LOCAL_CTAS, 256, 0, s_side>>>(q_hat, q_real);

    gemm_hinge_kernel<<<dim3(GRID_X, GRID_Y), 512, GEMM_SMEM_DYN>>>((float*)d_out);

    // Graph must join the side stream before capture ends.
    cudaEventRecord(ev_join, s_side);
    cudaStreamWaitEvent(0, ev_join, 0);
}

// round 10
// speedup vs baseline: 4.2699x; 4.2699x over previous
#include <cuda_runtime.h>
#include <cuda_bf16.h>
#include <cstdint>

// ---------------------------------------------------------------------------
// total = -(1/L) * sum_i dot(q_hat_i, q_real_i)
//       + sum_{i,j} max(0, <pred_i, gt_j> - <pred_i, gt_i> + 1)
// L=8192, B=4096, D=1024.
// R10: GEMM identical to R8 (best measured: 256 thr, warp tile 64x32, fp8,
// 3-stage, 2 CTA/SM, ~110 regs — the regfile ceiling; R9 proved 512-thr
// variants spill). New: prep with 4 rows/block (MLP 2->8) and finalize fused
// into the GEMM's last CTA via ticket (R9-proven), removing the tail launch.
// ---------------------------------------------------------------------------

#define L_DIM 8192
#define B_DIM 4096
#define D_DIM 1024

struct Accum {
    double glob;
    double local;
    unsigned int gticket;
    unsigned int lticket;
    unsigned int local_done;
};
__device__ Accum g_acc;
__device__ float g_pos[B_DIM];
// FP8 operand buffers (4 MB each), stored as uint32 (4 e4m3 per word)
__device__ uint32_t g_predq[(size_t)B_DIM * D_DIM / 4];
__device__ uint32_t g_gtq[(size_t)B_DIM * D_DIM / 4];

#define NUM_GEMM_CTAS (32 * 32)
#define NUM_LOCAL_CTAS 1024
#define PREP_ROWS 4

// ---------------------------------------------------------------------------
__device__ __forceinline__ uint32_t smem_u32(const void* p) {
    uint32_t a;
    asm("{ .reg .u64 t; cvta.to.shared.u64 t, %1; cvt.u32.u64 %0, t; }"
        : "=r"(a) : "l"(p));
    return a;
}

__device__ __forceinline__ void cp_async16(uint32_t smem, const void* gmem) {
    asm volatile("cp.async.cg.shared.global [%0], [%1], 16;"
                 :: "r"(smem), "l"(gmem) : "memory");
}
#define CP_COMMIT() asm volatile("cp.async.commit_group;" ::: "memory")
#define CP_WAIT1()  asm volatile("cp.async.wait_group 1;" ::: "memory")

#define LDSM_X4(r0, r1, r2, r3, addr) \
    asm volatile("ldmatrix.sync.aligned.m8n8.x4.shared.b16 {%0,%1,%2,%3}, [%4];" \
                 : "=r"(r0), "=r"(r1), "=r"(r2), "=r"(r3) : "r"(addr))

// FP8 e4m3 MMA, k32, fp32 accumulation.
__device__ __forceinline__ void mma16832(float* c, const uint32_t* a,
                                         uint32_t b0, uint32_t b1) {
    asm volatile(
        "mma.sync.aligned.m16n8k32.row.col.f32.e4m3.e4m3.f32 "
        "{%0,%1,%2,%3}, {%4,%5,%6,%7}, {%8,%9}, {%0,%1,%2,%3};"
        : "+f"(c[0]), "+f"(c[1]), "+f"(c[2]), "+f"(c[3])
        : "r"(a[0]), "r"(a[1]), "r"(a[2]), "r"(a[3]), "r"(b0), "r"(b1));
}

__device__ __forceinline__ uint32_t pack_e4m3x4(float4 v) {
    uint16_t lo, hi;
    asm("cvt.rn.satfinite.e4m3x2.f32 %0, %1, %2;" : "=h"(lo) : "f"(v.y), "f"(v.x));
    asm("cvt.rn.satfinite.e4m3x2.f32 %0, %1, %2;" : "=h"(hi) : "f"(v.w), "f"(v.z));
    return (uint32_t)lo | ((uint32_t)hi << 16);
}

// ---------------------------------------------------------------------------
// Kernel 1: fp32 -> e4m3 for pred/gt + pos[i] = dot(pred_i, gt_i) (exact fp32)
// 4 rows per block (8 independent 16B loads in flight per thread).
// grid = B_DIM/4, 256 threads.
// ---------------------------------------------------------------------------
__global__ void prep_kernel(const float* __restrict__ pred,
                            const float* __restrict__ gt) {
    const int r0 = blockIdx.x * PREP_ROWS;
    const int t = threadIdx.x;

    float4 pv[PREP_ROWS], gv[PREP_ROWS];
    #pragma unroll
    for (int rr = 0; rr < PREP_ROWS; rr++) {
        pv[rr] = ((const float4*)(pred + (size_t)(r0 + rr) * D_DIM))[t];
        gv[rr] = ((const float4*)(gt + (size_t)(r0 + rr) * D_DIM))[t];
    }

    __shared__ float ws[PREP_ROWS][8];
    #pragma unroll
    for (int rr = 0; rr < PREP_ROWS; rr++) {
        g_predq[(size_t)(r0 + rr) * (D_DIM / 4) + t] = pack_e4m3x4(pv[rr]);
        g_gtq[(size_t)(r0 + rr) * (D_DIM / 4) + t] = pack_e4m3x4(gv[rr]);

        float acc = pv[rr].x * gv[rr].x + pv[rr].y * gv[rr].y +
                    pv[rr].z * gv[rr].z + pv[rr].w * gv[rr].w;
        #pragma unroll
        for (int o = 16; o > 0; o >>= 1)
            acc += __shfl_xor_sync(0xFFFFFFFFu, acc, o);
        if ((t & 31) == 0) ws[rr][t >> 5] = acc;
    }
    __syncthreads();
    if (t < PREP_ROWS) {
        float s = 0.f;
        #pragma unroll
        for (int w = 0; w < 8; w++) s += ws[t][w];
        g_pos[r0 + t] = s;
    }
}

// ---------------------------------------------------------------------------
// Kernel 2: local loss partial (side stream; overlaps prep + GEMM).
// Last block sets local_done (release) for the GEMM's fused finalize.
// ---------------------------------------------------------------------------
__global__ void local_kernel(const float* __restrict__ a,
                             const float* __restrict__ b) {
    const size_t n4 = (size_t)L_DIM * D_DIM / 4;
    float acc = 0.f;
    for (size_t i = (size_t)blockIdx.x * blockDim.x + threadIdx.x; i < n4;
         i += (size_t)gridDim.x * blockDim.x) {
        float4 av = ((const float4*)a)[i];
        float4 bv = ((const float4*)b)[i];
        acc += av.x * bv.x + av.y * bv.y + av.z * bv.z + av.w * bv.w;
    }
    #pragma unroll
    for (int o = 16; o > 0; o >>= 1)
        acc += __shfl_xor_sync(0xFFFFFFFFu, acc, o);
    __shared__ float ws[8];
    const int t = threadIdx.x;
    if ((t & 31) == 0) ws[t >> 5] = acc;
    __syncthreads();
    if (t == 0) {
        float s = 0.f;
        #pragma unroll
        for (int w = 0; w < 8; w++) s += ws[w];
        atomicAdd(&g_acc.local, (double)s);
        __threadfence();
        unsigned int tk = atomicAdd(&g_acc.lticket, 1u);
        if (tk == NUM_LOCAL_CTAS - 1) {
            __threadfence();
            atomicExch(&g_acc.local_done, 1u);
        }
    }
}

// ---------------------------------------------------------------------------
// Kernel 3: FP8 GEMM 128x128 tile + fused hinge + fused finalize.
// Identical to R8's GEMM (grid (32,32), 256 thr, 8 warps 2x4, warp tile
// 64x32, 3-stage cp.async, 2 CTAs/SM) + last-CTA finalize ticket.
// ---------------------------------------------------------------------------
static constexpr int GEMM_SMEM_DYN = 3 * 32768;  // 96 KB

__global__ void __launch_bounds__(256, 2) gemm_hinge_kernel(float* out) {
    extern __shared__ char smem_raw[];
    const uint32_t sb = smem_u32(smem_raw);
    const int tid = threadIdx.x;
    const int wid = tid >> 5;
    const int lane = tid & 31;
    const int warp_m = wid >> 2;   // 0..1
    const int warp_n = wid & 3;    // 0..3

    const uint8_t* __restrict__ Ab =
        (const uint8_t*)g_predq + (size_t)blockIdx.y * 128 * D_DIM;
    const uint8_t* __restrict__ Bb =
        (const uint8_t*)g_gtq + (size_t)blockIdx.x * 128 * D_DIM;

    // Precomputed LDSM base offsets: addr = stage_base + (base ^ (chunk<<4))
    uint32_t a_base[4], b_base[2];
    #pragma unroll
    for (int mt = 0; mt < 4; mt++) {
        const int row = warp_m * 64 + mt * 16 + (lane & 15);
        a_base[mt] = row * 128 + (((lane >> 4) ^ (row & 7)) << 4);
    }
    #pragma unroll
    for (int nt = 0; nt < 2; nt++) {
        const int row = warp_n * 32 + nt * 16 + (lane & 15);
        b_base[nt] = row * 128 + (((lane >> 4) ^ (row & 7)) << 4);
    }

    float acc[4][4][4];
    #pragma unroll
    for (int i = 0; i < 4; i++)
        #pragma unroll
        for (int j = 0; j < 4; j++)
            #pragma unroll
            for (int e = 0; e < 4; e++) acc[i][j][e] = 0.f;

    // Load one K-chunk (128 B per row) of A and B into stage st.
    auto load_stage = [&](int kc, int st) {
        const uint32_t baseA = sb + st * 32768;
        const uint32_t baseB = baseA + 16384;
        #pragma unroll
        for (int i = 0; i < 4; i++) {
            const int idx = tid + i * 256;      // 0..1023
            const int row = idx >> 3;           // 0..127
            const int c = idx & 7;              // 16B chunk within 128B row
            const uint32_t soff = row * 128 + ((c ^ (row & 7)) << 4);
            cp_async16(baseA + soff, Ab + (size_t)row * D_DIM + kc * 128 + c * 16);
            cp_async16(baseB + soff, Bb + (size_t)row * D_DIM + kc * 128 + c * 16);
        }
    };

    load_stage(0, 0); CP_COMMIT();
    load_stage(1, 1); CP_COMMIT();

    #pragma unroll 1
    for (int kc = 0; kc < 8; ++kc) {
        CP_WAIT1();          // stage kc resident
        __syncthreads();     // all warps done with the stage we refill
        if (kc + 2 < 8) load_stage(kc + 2, (kc + 2) % 3);
        CP_COMMIT();         // uniform group count even when empty

        const uint32_t baseA = sb + (kc % 3) * 32768;
        const uint32_t baseB = baseA + 16384;

        #pragma unroll
        for (int ks = 0; ks < 4; ks++) {   // four k32 steps per 128-B chunk
            const uint32_t cx = (uint32_t)(ks * 2) << 4;  // chunk XOR offset
            uint32_t a[4][4], b[2][4];
            #pragma unroll
            for (int mt = 0; mt < 4; mt++)
                LDSM_X4(a[mt][0], a[mt][1], a[mt][2], a[mt][3],
                        baseA + (a_base[mt] ^ cx));
            #pragma unroll
            for (int nt = 0; nt < 2; nt++)
                LDSM_X4(b[nt][0], b[nt][1], b[nt][2], b[nt][3],
                        baseB + (b_base[nt] ^ cx));
            #pragma unroll
            for (int mt = 0; mt < 4; mt++)
                #pragma unroll
                for (int nt = 0; nt < 4; nt++)
                    mma16832(acc[mt][nt], a[mt],
                             b[nt >> 1][nt & 1], b[nt >> 1][(nt & 1) + 2]);
        }
    }

    // ---- fused hinge epilogue ----
    float partial = 0.f;
    #pragma unroll
    for (int mt = 0; mt < 4; mt++) {
        const int r0 = blockIdx.y * 128 + warp_m * 64 + mt * 16 + (lane >> 2);
        const float p0 = __ldg(&g_pos[r0]) - 1.0f;   // v - pos + 1 = v - (pos-1)
        const float p1 = __ldg(&g_pos[r0 + 8]) - 1.0f;
        #pragma unroll
        for (int nt = 0; nt < 4; nt++) {
            partial += fmaxf(acc[mt][nt][0] - p0, 0.f);
            partial += fmaxf(acc[mt][nt][1] - p0, 0.f);
            partial += fmaxf(acc[mt][nt][2] - p1, 0.f);
            partial += fmaxf(acc[mt][nt][3] - p1, 0.f);
        }
    }

    #pragma unroll
    for (int o = 16; o > 0; o >>= 1)
        partial += __shfl_xor_sync(0xFFFFFFFFu, partial, o);
    __shared__ float warpsum[8];
    if (lane == 0) warpsum[wid] = partial;
    __syncthreads();
    if (tid == 0) {
        float s = 0.f;
        #pragma unroll
        for (int w = 0; w < 8; w++) s += warpsum[w];
        atomicAdd(&g_acc.glob, (double)s);
        __threadfence();
        unsigned int tk = atomicAdd(&g_acc.gticket, 1u);
        if (tk == NUM_GEMM_CTAS - 1) {
            // Fused finalize: wait for local_kernel completion (side stream;
            // submitted before this kernel, independent of it — no deadlock;
            // verified working in R9).
            while (atomicAdd(&g_acc.local_done, 0u) == 0u) {}
            __threadfence();
            const double gv = *((volatile double*)&g_acc.glob);
            const double lv = *((volatile double*)&g_acc.local);
            out[0] = (float)(gv - lv / (double)L_DIM);
        }
    }
}

// ---------------------------------------------------------------------------
extern "C" void kernel_launch(void* const* d_in, const int* in_sizes, int n_in,
                              void* d_out, int out_size) {
    const float* q_hat  = (const float*)d_in[0];
    const float* q_real = (const float*)d_in[1];
    const float* gt     = (const float*)d_in[2];
    const float* pred   = (const float*)d_in[3];

    (void)in_sizes; (void)n_in; (void)out_size;

    // One-time setup on the first (non-captured) correctness call.
    static cudaStream_t s_side = nullptr;
    static cudaEvent_t ev_fork = nullptr, ev_join = nullptr;
    static void* accum_ptr = nullptr;
    if (!accum_ptr) {
        cudaFuncSetAttribute(gemm_hinge_kernel,
                             cudaFuncAttributeMaxDynamicSharedMemorySize,
                             GEMM_SMEM_DYN);
        cudaStreamCreateWithFlags(&s_side, cudaStreamNonBlocking);
        cudaEventCreateWithFlags(&ev_fork, cudaEventDisableTiming);
        cudaEventCreateWithFlags(&ev_join, cudaEventDisableTiming);
        cudaGetSymbolAddress(&accum_ptr, g_acc);
    }

    // Main stream: memset -> prep -> gemm(+finalize)
    // Side stream: local_kernel (independent; overlaps prep + gemm)
    cudaMemsetAsync(accum_ptr, 0, sizeof(Accum), 0);
    cudaEventRecord(ev_fork, 0);
    cudaStreamWaitEvent(s_side, ev_fork, 0);

    prep_kernel<<<B_DIM / PREP_ROWS, 256>>>(pred, gt);
    local_kernel<<<NUM_LOCAL_CTAS, 256, 0, s_side>>>(q_hat, q_real);

    gemm_hinge_kernel<<<dim3(32, 32), 256, GEMM_SMEM_DYN>>>((float*)d_out);

    // Graph must join the side stream before capture ends.
    cudaEventRecord(ev_join, s_side);
    cudaStreamWaitEvent(0, ev_join, 0);
}